// round 15
// baseline (speedup 1.0000x reference)
#include <cuda_runtime.h>
#include <cuda_fp16.h>
#include <cstdint>
#include <math.h>

// ============================================================================
// Scratch (allocation-free rule: __device__ globals)
// ============================================================================
__device__ unsigned short g_qkv[4096 * 4096];   // fp16: q 0-2047 | k 2048-3071 | v 3072-4095
__device__ float g_bias[4096];                  // bq | bk | bv
__device__ unsigned short g_hsh[8388608];       // hs fp16
__device__ unsigned short g_wqkvh[8388608];     // Wq | Wk | Wv rows x 2048
__device__ unsigned short g_woh[4194304];
__device__ unsigned short g_rh[8192];           // R fp16 [64 x 128]
__device__ unsigned short g_nx[4096 * 24 * 128];// normalized rope'd q/k rows, fp16
__device__ float g_p[4096 * 24 * 64];           // projections, fp32
__device__ unsigned short g_xh[8388608];        // X fp16 (reshape-quirk layout)

// ============================================================================
// Helpers
// ============================================================================
__device__ __forceinline__ uint32_t smem_u32(const void* p) {
    uint32_t a;
    asm("{ .reg .u64 t; cvta.to.shared.u64 t, %1; cvt.u32.u64 %0, t; }" : "=r"(a) : "l"(p));
    return a;
}
__device__ __forceinline__ void cp16(uint32_t soff, const void* g) {
    asm volatile("cp.async.cg.shared.global [%0], [%1], 16;" :: "r"(soff), "l"(g));
}
__device__ __forceinline__ void cp_commit() { asm volatile("cp.async.commit_group;"); }
__device__ __forceinline__ void cp_wait0()  { asm volatile("cp.async.wait_group 0;" ::: "memory"); }
__device__ __forceinline__ void cp_wait1()  { asm volatile("cp.async.wait_group 1;" ::: "memory"); }

__device__ __forceinline__ void ldm_x4(uint32_t* r, uint32_t addr) {
    asm volatile("ldmatrix.sync.aligned.m8n8.x4.shared.b16 {%0,%1,%2,%3}, [%4];"
                 : "=r"(r[0]), "=r"(r[1]), "=r"(r[2]), "=r"(r[3]) : "r"(addr));
}
__device__ __forceinline__ void mma16816(float* c, const uint32_t* a, const uint32_t* b) {
    asm volatile(
        "mma.sync.aligned.m16n8k16.row.col.f32.f16.f16.f32 "
        "{%0,%1,%2,%3}, {%4,%5,%6,%7}, {%8,%9}, {%0,%1,%2,%3};"
        : "+f"(c[0]), "+f"(c[1]), "+f"(c[2]), "+f"(c[3])
        : "r"(a[0]), "r"(a[1]), "r"(a[2]), "r"(a[3]), "r"(b[0]), "r"(b[1]));
}

__device__ __forceinline__ void store_pair(float* C, size_t off, float a, float b) {
    *(float2*)&C[off] = make_float2(a, b);
}
__device__ __forceinline__ void store_pair(__half* C, size_t off, float a, float b) {
    *(__half2*)&C[off] = __floats2half2_rn(a, b);
}

// ============================================================================
// One fused conversion kernel: all fp32->fp16 converts + bias concat.
// ============================================================================
#define H0 2097152
#define H1 3145728
#define H2 3670016
#define H3 4194304
#define H4 5242880
#define H5 5244928
#define H6 5245952

__global__ __launch_bounds__(256)
void convert_all(const float* __restrict__ hs, const float* __restrict__ Wq,
                 const float* __restrict__ Wk, const float* __restrict__ Wv,
                 const float* __restrict__ Wo, const float* __restrict__ R,
                 const float* __restrict__ bq, const float* __restrict__ bk,
                 const float* __restrict__ bv,
                 unsigned short* __restrict__ hsh, unsigned short* __restrict__ wqkvh,
                 unsigned short* __restrict__ woh, unsigned short* __restrict__ rh,
                 float* __restrict__ gb)
{
    int idx = blockIdx.x * 256 + threadIdx.x;
    if (idx >= H6) return;

    if (idx >= H5) {
        int i = idx - H5;
        float4 v;
        if (i < 512)      v = ((const float4*)bq)[i];
        else if (i < 768) v = ((const float4*)bk)[i - 512];
        else              v = ((const float4*)bv)[i - 768];
        ((float4*)gb)[i] = v;
        return;
    }

    const float* src;
    unsigned short* dst;
    int di;
    if (idx < H0)      { src = hs; di = idx;       dst = hsh; }
    else if (idx < H1) { src = Wq; di = idx - H0;  dst = wqkvh; }
    else if (idx < H2) { src = Wk; di = idx - H1;  dst = wqkvh + 4194304; }
    else if (idx < H3) { src = Wv; di = idx - H2;  dst = wqkvh + 6291456; }
    else if (idx < H4) { src = Wo; di = idx - H3;  dst = woh; }
    else               { src = R;  di = idx - H4;  dst = rh; }

    float4 x = ((const float4*)src)[di];
    __half2 a = __floats2half2_rn(x.x, x.y);
    __half2 b = __floats2half2_rn(x.z, x.w);
    uint2 H;
    H.x = *(uint32_t*)&a;  H.y = *(uint32_t*)&b;
    ((uint2*)dst)[di] = H;
}

// ============================================================================
// mma.sync fp16 GEMM:  C[M,N] = A[M,K] @ B[N,K]^T + bias[N]
// Block 128x128x64, 256 threads, 8 warps (2m x 4n), warp tile 64x32.
// 3-stage cp.async pipeline, 2 CTAs/SM.
// ROUND-15 change (only): B fragments register double-buffered (+8 regs) —
// each kb step's 2 B-ldsm for kb+1 issue during kb's MMAs, so only the 4
// A-ldsm remain exposed at the head of each kb. MMA order unchanged.
// ============================================================================
#define GBK 64
#define APITCH 72
#define ROW_B  144
#define OFF_B  18432                     // A: 128 rows * 144
#define STAGE_B 36864                    // + B: 128 rows * 144
#define NSTAGE 3
#define GEMM_SMEM (NSTAGE * STAGE_B)     // 110592

template <typename OutT>
__global__ __launch_bounds__(256, 2)
void gemm_f16(const unsigned short* __restrict__ Ah, const unsigned short* __restrict__ Bh,
              const float* __restrict__ bias, OutT* __restrict__ C,
              int M, int N, int K)
{
    extern __shared__ __align__(128) char smem[];
    const uint32_t sb = smem_u32(smem);
    const int tid = threadIdx.x, wid = tid >> 5, lane = tid & 31;
    const int bm = blockIdx.y * 128, bn = blockIdx.x * 128;
    const int m0w = (wid & 1) * 64, n0w = (wid >> 1) * 32;

    float c[4][4][4];
#pragma unroll
    for (int i = 0; i < 4; i++)
#pragma unroll
        for (int j = 0; j < 4; j++)
#pragma unroll
            for (int r = 0; r < 4; r++) c[i][j][r] = 0.f;

    const int rowA = lane & 15, kselA = (lane >> 4) * 8;
    const int grpB = lane >> 3, rowB = lane & 7;
    const int nAdd = rowB + ((grpB & 2) ? 8 : 0);
    const int kAdd = (grpB & 1) * 8;

    const int nk = K / GBK;

    auto load_stage = [&](int kt, int buf) {
        const int k0 = kt * GBK;
        const uint32_t stb = sb + buf * STAGE_B;
#pragma unroll
        for (int it = 0; it < 8; it++) {
            int cc = it * 256 + tid;               // 0..2047
            if (cc < 1024) {
                int row = cc >> 3, ch = cc & 7;
                cp16(stb + row * ROW_B + ch * 16,
                     Ah + (size_t)(bm + row) * K + k0 + ch * 8);
            } else {
                int idx = cc - 1024, row = idx >> 3, ch = idx & 7;
                cp16(stb + OFF_B + row * ROW_B + ch * 16,
                     Bh + (size_t)(bn + row) * K + k0 + ch * 8);
            }
        }
    };

    load_stage(0, 0); cp_commit();
    load_stage(1, 1); cp_commit();

    uint32_t bh[2][2][4];

    for (int kt = 0; kt < nk; kt++) {
        if (kt + 1 < nk) cp_wait1();
        else             cp_wait0();
        __syncthreads();

        const int buf = kt % 3;
        const uint32_t sA = sb + buf * STAGE_B;
        const uint32_t sB = sA + OFF_B;

        // prime B fragments for kb=0
#pragma unroll
        for (int jj = 0; jj < 2; jj++) {
            uint32_t addr = sB + ((n0w + 16 * jj + nAdd) * APITCH + kAdd) * 2;
            ldm_x4(bh[0][jj], addr);
        }

#pragma unroll
        for (int kb = 0; kb < 4; kb++) {
            const int cur = kb & 1;
            const int kcol = kb * 16;
            uint32_t ah[4][4];
#pragma unroll
            for (int i = 0; i < 4; i++) {
                uint32_t addr = sA + ((m0w + 16 * i + rowA) * APITCH + kcol + kselA) * 2;
                ldm_x4(ah[i], addr);
            }
            if (kb < 3) {
                const int kn = kcol + 16;
#pragma unroll
                for (int jj = 0; jj < 2; jj++) {
                    uint32_t addr = sB + ((n0w + 16 * jj + nAdd) * APITCH + kn + kAdd) * 2;
                    ldm_x4(bh[cur ^ 1][jj], addr);
                }
            }
#pragma unroll
            for (int i = 0; i < 4; i++)
#pragma unroll
                for (int j = 0; j < 4; j++)
                    mma16816(c[i][j], ah[i], &bh[cur][j >> 1][(j & 1) * 2]);
        }

        if (kt + 2 < nk) { load_stage(kt + 2, (kt + 2) % 3); cp_commit(); }
    }

    const int r0 = lane >> 2, cc2 = (lane & 3) * 2;
#pragma unroll
    for (int i = 0; i < 4; i++) {
#pragma unroll
        for (int j = 0; j < 4; j++) {
            int row = bm + m0w + 16 * i + r0;
            int col = bn + n0w + 8 * j + cc2;
            float b0 = bias[col], b1 = bias[col + 1];
            store_pair(C, (size_t)row * N + col,       c[i][j][0] + b0, c[i][j][1] + b1);
            store_pair(C, (size_t)(row + 8) * N + col, c[i][j][2] + b0, c[i][j][3] + b1);
        }
    }
}

// ============================================================================
// token_pre: RoPE(q,k) + row normalization -> nx[token*24 + r, 128] fp16
// (frozen)
// ============================================================================
__global__ __launch_bounds__(256)
void token_pre(const unsigned short* __restrict__ gqkv, unsigned short* __restrict__ nx)
{
    __shared__ float sX[3072];
    __shared__ float sSin[64], sCos[64];
    __shared__ float sRinv[24];

    const int t = threadIdx.x, w = t >> 5, lane = t & 31;
    const int token = blockIdx.x, s = token & 2047;

    if (t < 64) {
        float iv = (float)exp(-(double)t * 0.14391156831212787);  // ln(1e4)/64
        float ang = (float)s * iv;
        sincosf(ang, &sSin[t], &sCos[t]);
    }
    __syncthreads();

    const size_t base = (size_t)token * 4096;
    const __half* q = (const __half*)(gqkv + base);
#pragma unroll
    for (int it = 0; it < 12; it++) {
        int i = it * 256 + t;
        int d = i & 127, j = d & 63;
        float val = __half2float(q[i]);
        float oth = __half2float(q[(i & ~127) + ((d < 64) ? d + 64 : d - 64)]);
        sX[i] = val * sCos[j] + ((d < 64) ? -oth : oth) * sSin[j];
    }
    __syncthreads();

    for (int r = w; r < 24; r += 8) {
        const float* src = sX + r * 128;
        float ss = 0.f;
#pragma unroll
        for (int d = lane; d < 128; d += 32) { float x = src[d]; ss += x * x; }
#pragma unroll
        for (int o = 16; o; o >>= 1) ss += __shfl_xor_sync(0xffffffffu, ss, o);
        if (lane == 0) sRinv[r] = 1.0f / fmaxf(sqrtf(ss), 1e-6f);
    }
    __syncthreads();

    unsigned short* dst = nx + (size_t)token * 3072;
#pragma unroll
    for (int it = 0; it < 6; it++) {
        int i2 = (it * 256 + t) * 2;
        int r = i2 >> 7;
        __half2 hv = __floats2half2_rn(sX[i2] * sRinv[r], sX[i2 + 1] * sRinv[r]);
        *(__half2*)(dst + i2) = hv;
    }
}

// ============================================================================
// gemm_p: P[98304, 64] = nx[98304, 128] @ R[64, 128]^T   (one-shot K=128)
// (frozen)
// ============================================================================
#define PP 136
#define P_OFF_B (256 * 272)
#define P_SMEM  (P_OFF_B + 64 * 272)     // 87040

__global__ __launch_bounds__(256, 1)
void gemm_p(const unsigned short* __restrict__ nx, const unsigned short* __restrict__ Rh,
            float* __restrict__ P)
{
    extern __shared__ __align__(128) char smem[];
    const uint32_t sb = smem_u32(smem);
    const int tid = threadIdx.x, wid = tid >> 5, lane = tid & 31;
    const int bm = blockIdx.x * 256;
    const int m0w = (wid & 3) * 64, n0w = (wid >> 2) * 32;

#pragma unroll
    for (int it = 0; it < 20; it++) {
        int cc = it * 256 + tid;
        if (cc < 4096) {
            int row = cc >> 4, ch = cc & 15;
            cp16(sb + row * 272 + ch * 16, nx + (size_t)(bm + row) * 128 + ch * 8);
        } else {
            int idx = cc - 4096, row = idx >> 4, ch = idx & 15;
            cp16(sb + P_OFF_B + row * 272 + ch * 16, Rh + (size_t)row * 128 + ch * 8);
        }
    }
    cp_commit();
    cp_wait0();
    __syncthreads();

    const int rowA = lane & 15, kselA = (lane >> 4) * 8;
    const int grpB = lane >> 3, rowB = lane & 7;
    const int nAdd = rowB + ((grpB & 2) ? 8 : 0);
    const int kAdd = (grpB & 1) * 8;

    float c[4][4][4];
#pragma unroll
    for (int i = 0; i < 4; i++)
#pragma unroll
        for (int j = 0; j < 4; j++)
#pragma unroll
            for (int r = 0; r < 4; r++) c[i][j][r] = 0.f;

#pragma unroll
    for (int ks = 0; ks < 8; ks++) {
        const int kcol = ks * 16;
        uint32_t ah[4][4];
#pragma unroll
        for (int i = 0; i < 4; i++) {
            uint32_t addr = sb + ((m0w + 16 * i + rowA) * PP + kcol + kselA) * 2;
            ldm_x4(ah[i], addr);
        }
        uint32_t bh[2][4];
#pragma unroll
        for (int jj = 0; jj < 2; jj++) {
            uint32_t addr = sb + P_OFF_B + ((n0w + 16 * jj + nAdd) * PP + kcol + kAdd) * 2;
            ldm_x4(bh[jj], addr);
        }
#pragma unroll
        for (int i = 0; i < 4; i++)
#pragma unroll
            for (int j = 0; j < 4; j++)
                mma16816(c[i][j], ah[i], &bh[j >> 1][(j & 1) * 2]);
    }

    const int r0 = lane >> 2, cc2 = (lane & 3) * 2;
#pragma unroll
    for (int i = 0; i < 4; i++) {
#pragma unroll
        for (int j = 0; j < 4; j++) {
            int row = bm + m0w + 16 * i + r0;
            int col = n0w + 8 * j + cc2;
            *(float2*)&P[(size_t)row * 64 + col]       = make_float2(c[i][j][0], c[i][j][1]);
            *(float2*)&P[(size_t)(row + 8) * 64 + col] = make_float2(c[i][j][2], c[i][j][3]);
        }
    }
}

// ============================================================================
// token_post (vectorized, frozen from round 14): feats; scores; out = A @ V.
// ============================================================================
__global__ __launch_bounds__(256)
void token_post(const float* __restrict__ gP, const unsigned short* __restrict__ gqkv,
                unsigned short* __restrict__ gxh)
{
    __shared__ float sQP[16 * 132];
    __shared__ float sKP[8 * 132];
    __shared__ float sV[1024];
    __shared__ float sA[128];

    const int t = threadIdx.x;
    const int token = blockIdx.x, b = token >> 11, s = token & 2047;
    const float INVSF = 0.08838834764831845f;  // 1/sqrt(128)

    const float* P = gP + (size_t)token * 1536;
#pragma unroll
    for (int it = 0; it < 6; it++) {
        int i = it * 256 + t;
        int r = i >> 6, e = i & 63;
        float p = P[i];
        float sp, cp;
        __sincosf(p, &sp, &cp);
        float* dst = (r < 16) ? sQP + r * 132 : sKP + (r - 16) * 132;
        dst[e] = sp * INVSF;
        dst[e + 64] = cp * INVSF;
    }
    {
        const __half* v = (const __half*)(gqkv + (size_t)token * 4096 + 3072);
        uint2 raw = *(const uint2*)(v + t * 4);
        __half2 h0 = *(__half2*)&raw.x;
        __half2 h1 = *(__half2*)&raw.y;
        float2 f0 = __half22float2(h0);
        float2 f1 = __half22float2(h1);
        sV[t * 4 + 0] = f0.x;  sV[t * 4 + 1] = f0.y;
        sV[t * 4 + 2] = f1.x;  sV[t * 4 + 3] = f1.y;
    }
    __syncthreads();

    if (t < 128) {
        int h = t >> 3, i = t & 7;
        const float4* qp = (const float4*)(sQP + h * 132);
        const float4* kp = (const float4*)(sKP + i * 132);
        float acc = 0.f;
#pragma unroll
        for (int f4 = 0; f4 < 32; f4++) {
            float4 a = qp[f4], bb = kp[f4];
            acc += a.x * bb.x;
            acc += a.y * bb.y;
            acc += a.z * bb.z;
            acc += a.w * bb.w;
        }
        sA[t] = 2.0f * acc;
    }
    __syncthreads();

    const size_t obase = ((size_t)b << 22) + (size_t)((s & 15) << 7);
    const int rlo = s >> 4;
#pragma unroll
    for (int it = 0; it < 4; it++) {
        int idx = it * 256 + t;            // 0..1023 (h, d-pair)
        int h = idx >> 6, d = (idx & 63) * 2;
        float ax = 0.f, ay = 0.f;
#pragma unroll
        for (int i = 0; i < 8; i++) {
            float a = sA[h * 8 + i];
            float2 vv = *(const float2*)&sV[i * 128 + d];
            ax += a * vv.x;
            ay += a * vv.y;
        }
        size_t oi = obase + (size_t)(h * 128 + rlo) * 2048 + d;
        *(__half2*)(gxh + oi) = __floats2half2_rn(ax, ay);
    }
}

// ============================================================================
// Launch
// ============================================================================
extern "C" void kernel_launch(void* const* d_in, const int* in_sizes, int n_in,
                              void* d_out, int out_size)
{
    const float* hs = (const float*)d_in[0];
    const float* Wq = (const float*)d_in[1];
    const float* bq = (const float*)d_in[2];
    const float* Wk = (const float*)d_in[3];
    const float* bk = (const float*)d_in[4];
    const float* Wv = (const float*)d_in[5];
    const float* bv = (const float*)d_in[6];
    const float* Wo = (const float*)d_in[7];
    const float* bo = (const float*)d_in[8];
    const float* R  = (const float*)d_in[9];
    float* out = (float*)d_out;
    (void)in_sizes; (void)n_in; (void)out_size;

    unsigned short *qkv, *hsh, *wqkvh, *woh, *rh, *nx, *xh;
    float *gb, *gp;
    cudaGetSymbolAddress((void**)&qkv, g_qkv);
    cudaGetSymbolAddress((void**)&gb, g_bias);
    cudaGetSymbolAddress((void**)&hsh, g_hsh);
    cudaGetSymbolAddress((void**)&wqkvh, g_wqkvh);
    cudaGetSymbolAddress((void**)&woh, g_woh);
    cudaGetSymbolAddress((void**)&rh, g_rh);
    cudaGetSymbolAddress((void**)&nx, g_nx);
    cudaGetSymbolAddress((void**)&gp, g_p);
    cudaGetSymbolAddress((void**)&xh, g_xh);

    cudaFuncSetAttribute(gemm_f16<float>, cudaFuncAttributeMaxDynamicSharedMemorySize, GEMM_SMEM);
    cudaFuncSetAttribute(gemm_f16<__half>, cudaFuncAttributeMaxDynamicSharedMemorySize, GEMM_SMEM);
    cudaFuncSetAttribute(gemm_p, cudaFuncAttributeMaxDynamicSharedMemorySize, P_SMEM);

    // all conversions + bias concat in one launch
    convert_all<<<20492, 256>>>(hs, Wq, Wk, Wv, Wo, R, bq, bk, bv,
                                hsh, wqkvh, woh, rh, gb);

    // fused Q+K+V projection (fp16 out): 128x128 tiles, 2 CTAs/SM
    gemm_f16<__half><<<dim3(32, 32), 256, GEMM_SMEM>>>(
        hsh, wqkvh, gb, (__half*)qkv, 4096, 4096, 2048);

    // performer core: RoPE+norm -> projection GEMM -> feats/scores/out
    token_pre<<<4096, 256>>>(qkv, nx);
    gemm_p<<<384, 256, P_SMEM>>>(nx, rh, gp);
    token_post<<<4096, 256>>>(gp, qkv, xh);

    // output projection (fp32 out)
    gemm_f16<float><<<dim3(16, 32), 256, GEMM_SMEM>>>(
        xh, woh, bo, out, 4096, 2048, 2048);
}

// round 16
// speedup vs baseline: 1.0392x; 1.0392x over previous
#include <cuda_runtime.h>
#include <cuda_fp16.h>
#include <cstdint>
#include <math.h>

// ============================================================================
// Scratch (allocation-free rule: __device__ globals)
// ============================================================================
__device__ unsigned short g_qkv[4096 * 4096];   // fp16: q 0-2047 | k 2048-3071 | v 3072-4095
__device__ float g_bias[4096];                  // bq | bk | bv
__device__ unsigned short g_hsh[8388608];       // hs fp16
__device__ unsigned short g_wqkvh[8388608];     // Wq | Wk | Wv rows x 2048
__device__ unsigned short g_woh[4194304];
__device__ unsigned short g_rh[8192];           // R fp16 [64 x 128]
__device__ unsigned short g_nx[4096 * 24 * 128];// normalized rope'd q/k rows, fp16
__device__ float g_p[4096 * 24 * 64];           // projections, fp32
__device__ unsigned short g_xh[8388608];        // X fp16 (reshape-quirk layout)

// ============================================================================
// Helpers
// ============================================================================
__device__ __forceinline__ uint32_t smem_u32(const void* p) {
    uint32_t a;
    asm("{ .reg .u64 t; cvta.to.shared.u64 t, %1; cvt.u32.u64 %0, t; }" : "=r"(a) : "l"(p));
    return a;
}
__device__ __forceinline__ void cp16(uint32_t soff, const void* g) {
    asm volatile("cp.async.cg.shared.global [%0], [%1], 16;" :: "r"(soff), "l"(g));
}
__device__ __forceinline__ void cp_commit() { asm volatile("cp.async.commit_group;"); }
__device__ __forceinline__ void cp_wait0()  { asm volatile("cp.async.wait_group 0;" ::: "memory"); }
__device__ __forceinline__ void cp_wait1()  { asm volatile("cp.async.wait_group 1;" ::: "memory"); }

__device__ __forceinline__ void ldm_x4(uint32_t* r, uint32_t addr) {
    asm volatile("ldmatrix.sync.aligned.m8n8.x4.shared.b16 {%0,%1,%2,%3}, [%4];"
                 : "=r"(r[0]), "=r"(r[1]), "=r"(r[2]), "=r"(r[3]) : "r"(addr));
}
__device__ __forceinline__ void mma16816(float* c, const uint32_t* a, const uint32_t* b) {
    asm volatile(
        "mma.sync.aligned.m16n8k16.row.col.f32.f16.f16.f32 "
        "{%0,%1,%2,%3}, {%4,%5,%6,%7}, {%8,%9}, {%0,%1,%2,%3};"
        : "+f"(c[0]), "+f"(c[1]), "+f"(c[2]), "+f"(c[3])
        : "r"(a[0]), "r"(a[1]), "r"(a[2]), "r"(a[3]), "r"(b[0]), "r"(b[1]));
}

__device__ __forceinline__ void store_pair(float* C, size_t off, float a, float b) {
    *(float2*)&C[off] = make_float2(a, b);
}
__device__ __forceinline__ void store_pair(__half* C, size_t off, float a, float b) {
    *(__half2*)&C[off] = __floats2half2_rn(a, b);
}

// ============================================================================
// One fused conversion kernel: all fp32->fp16 converts + bias concat.
// ============================================================================
#define H0 2097152
#define H1 3145728
#define H2 3670016
#define H3 4194304
#define H4 5242880
#define H5 5244928
#define H6 5245952

__global__ __launch_bounds__(256)
void convert_all(const float* __restrict__ hs, const float* __restrict__ Wq,
                 const float* __restrict__ Wk, const float* __restrict__ Wv,
                 const float* __restrict__ Wo, const float* __restrict__ R,
                 const float* __restrict__ bq, const float* __restrict__ bk,
                 const float* __restrict__ bv,
                 unsigned short* __restrict__ hsh, unsigned short* __restrict__ wqkvh,
                 unsigned short* __restrict__ woh, unsigned short* __restrict__ rh,
                 float* __restrict__ gb)
{
    int idx = blockIdx.x * 256 + threadIdx.x;
    if (idx >= H6) return;

    if (idx >= H5) {
        int i = idx - H5;
        float4 v;
        if (i < 512)      v = ((const float4*)bq)[i];
        else if (i < 768) v = ((const float4*)bk)[i - 512];
        else              v = ((const float4*)bv)[i - 768];
        ((float4*)gb)[i] = v;
        return;
    }

    const float* src;
    unsigned short* dst;
    int di;
    if (idx < H0)      { src = hs; di = idx;       dst = hsh; }
    else if (idx < H1) { src = Wq; di = idx - H0;  dst = wqkvh; }
    else if (idx < H2) { src = Wk; di = idx - H1;  dst = wqkvh + 4194304; }
    else if (idx < H3) { src = Wv; di = idx - H2;  dst = wqkvh + 6291456; }
    else if (idx < H4) { src = Wo; di = idx - H3;  dst = woh; }
    else               { src = R;  di = idx - H4;  dst = rh; }

    float4 x = ((const float4*)src)[di];
    __half2 a = __floats2half2_rn(x.x, x.y);
    __half2 b = __floats2half2_rn(x.z, x.w);
    uint2 H;
    H.x = *(uint32_t*)&a;  H.y = *(uint32_t*)&b;
    ((uint2*)dst)[di] = H;
}

// ============================================================================
// mma.sync fp16 GEMM:  C[M,N] = A[M,K] @ B[N,K]^T + bias[N]
// Block 128x128x64, 256 threads, 8 warps (2m x 4n), warp tile 64x32.
// 3-stage cp.async pipeline, 2 CTAs/SM.
// FROZEN round-14 body: three mainloop reorderings (R9, R10/11, R15) all
// regressed — ptxas schedules the straight-line body better than any of them.
// ============================================================================
#define GBK 64
#define APITCH 72
#define ROW_B  144
#define OFF_B  18432                     // A: 128 rows * 144
#define STAGE_B 36864                    // + B: 128 rows * 144
#define NSTAGE 3
#define GEMM_SMEM (NSTAGE * STAGE_B)     // 110592

template <typename OutT>
__global__ __launch_bounds__(256, 2)
void gemm_f16(const unsigned short* __restrict__ Ah, const unsigned short* __restrict__ Bh,
              const float* __restrict__ bias, OutT* __restrict__ C,
              int M, int N, int K)
{
    extern __shared__ __align__(128) char smem[];
    const uint32_t sb = smem_u32(smem);
    const int tid = threadIdx.x, wid = tid >> 5, lane = tid & 31;
    const int bm = blockIdx.y * 128, bn = blockIdx.x * 128;
    const int m0w = (wid & 1) * 64, n0w = (wid >> 1) * 32;

    float c[4][4][4];
#pragma unroll
    for (int i = 0; i < 4; i++)
#pragma unroll
        for (int j = 0; j < 4; j++)
#pragma unroll
            for (int r = 0; r < 4; r++) c[i][j][r] = 0.f;

    const int rowA = lane & 15, kselA = (lane >> 4) * 8;
    const int grpB = lane >> 3, rowB = lane & 7;
    const int nAdd = rowB + ((grpB & 2) ? 8 : 0);
    const int kAdd = (grpB & 1) * 8;

    const int nk = K / GBK;

    auto load_stage = [&](int kt, int buf) {
        const int k0 = kt * GBK;
        const uint32_t stb = sb + buf * STAGE_B;
#pragma unroll
        for (int it = 0; it < 8; it++) {
            int cc = it * 256 + tid;               // 0..2047
            if (cc < 1024) {
                int row = cc >> 3, ch = cc & 7;
                cp16(stb + row * ROW_B + ch * 16,
                     Ah + (size_t)(bm + row) * K + k0 + ch * 8);
            } else {
                int idx = cc - 1024, row = idx >> 3, ch = idx & 7;
                cp16(stb + OFF_B + row * ROW_B + ch * 16,
                     Bh + (size_t)(bn + row) * K + k0 + ch * 8);
            }
        }
    };

    load_stage(0, 0); cp_commit();
    load_stage(1, 1); cp_commit();

    for (int kt = 0; kt < nk; kt++) {
        if (kt + 1 < nk) cp_wait1();
        else             cp_wait0();
        __syncthreads();

        const int buf = kt % 3;
        const uint32_t sA = sb + buf * STAGE_B;
        const uint32_t sB = sA + OFF_B;

#pragma unroll
        for (int kb = 0; kb < 4; kb++) {
            const int kcol = kb * 16;
            uint32_t ah[4][4];
#pragma unroll
            for (int i = 0; i < 4; i++) {
                uint32_t addr = sA + ((m0w + 16 * i + rowA) * APITCH + kcol + kselA) * 2;
                ldm_x4(ah[i], addr);
            }
            uint32_t bh[2][4];
#pragma unroll
            for (int jj = 0; jj < 2; jj++) {
                uint32_t addr = sB + ((n0w + 16 * jj + nAdd) * APITCH + kcol + kAdd) * 2;
                ldm_x4(bh[jj], addr);
            }
#pragma unroll
            for (int i = 0; i < 4; i++)
#pragma unroll
                for (int j = 0; j < 4; j++)
                    mma16816(c[i][j], ah[i], &bh[j >> 1][(j & 1) * 2]);
        }

        if (kt + 2 < nk) { load_stage(kt + 2, (kt + 2) % 3); cp_commit(); }
    }

    const int r0 = lane >> 2, cc2 = (lane & 3) * 2;
#pragma unroll
    for (int i = 0; i < 4; i++) {
#pragma unroll
        for (int j = 0; j < 4; j++) {
            int row = bm + m0w + 16 * i + r0;
            int col = bn + n0w + 8 * j + cc2;
            float b0 = bias[col], b1 = bias[col + 1];
            store_pair(C, (size_t)row * N + col,       c[i][j][0] + b0, c[i][j][1] + b1);
            store_pair(C, (size_t)(row + 8) * N + col, c[i][j][2] + b0, c[i][j][3] + b1);
        }
    }
}

// ============================================================================
// token_pre (vectorized loads): RoPE(q,k) + row normalization -> nx fp16.
// Quad-aligned uint2 loads (value + RoPE partner); per-element FP math and
// order identical to the scalar version -> bit-identical output.
// ============================================================================
__global__ __launch_bounds__(256)
void token_pre(const unsigned short* __restrict__ gqkv, unsigned short* __restrict__ nx)
{
    __shared__ float sX[3072];
    __shared__ float sSin[64], sCos[64];
    __shared__ float sRinv[24];

    const int t = threadIdx.x, w = t >> 5, lane = t & 31;
    const int token = blockIdx.x, s = token & 2047;

    if (t < 64) {
        float iv = (float)exp(-(double)t * 0.14391156831212787);  // ln(1e4)/64
        float ang = (float)s * iv;
        sincosf(ang, &sSin[t], &sCos[t]);
    }
    __syncthreads();

    const size_t base = (size_t)token * 4096;
    const __half* q = (const __half*)(gqkv + base);
    // 3072 elements as 768 aligned quads; quads never straddle the 64-col
    // rotate boundary, and the +-64 partner quad stays 4-aligned.
#pragma unroll
    for (int it = 0; it < 3; it++) {
        int qd = it * 256 + t;                 // 0..767
        int i = qd * 4;
        int d = i & 127;
        const __half* rowp = q + (i & ~127);
        uint2 vraw = *(const uint2*)(rowp + d);
        int pd = (d < 64) ? d + 64 : d - 64;
        uint2 oraw = *(const uint2*)(rowp + pd);
        const __half* vh = (const __half*)&vraw;
        const __half* oh = (const __half*)&oraw;
#pragma unroll
        for (int e = 0; e < 4; e++) {
            int de = d + e, j = de & 63;
            float val = __half2float(vh[e]);
            float oth = __half2float(oh[e]);
            sX[i + e] = val * sCos[j] + ((de < 64) ? -oth : oth) * sSin[j];
        }
    }
    __syncthreads();

    for (int r = w; r < 24; r += 8) {
        const float* src = sX + r * 128;
        float ss = 0.f;
#pragma unroll
        for (int d = lane; d < 128; d += 32) { float x = src[d]; ss += x * x; }
#pragma unroll
        for (int o = 16; o; o >>= 1) ss += __shfl_xor_sync(0xffffffffu, ss, o);
        if (lane == 0) sRinv[r] = 1.0f / fmaxf(sqrtf(ss), 1e-6f);
    }
    __syncthreads();

    // store: 768 quads, one ushort4 each (same __floats2half2_rn packing)
    unsigned short* dst = nx + (size_t)token * 3072;
#pragma unroll
    for (int it = 0; it < 3; it++) {
        int qd = it * 256 + t;
        int i = qd * 4;
        int r = i >> 7;
        float rv = sRinv[r];
        __half2 h0 = __floats2half2_rn(sX[i] * rv, sX[i + 1] * rv);
        __half2 h1 = __floats2half2_rn(sX[i + 2] * rv, sX[i + 3] * rv);
        uint2 packed;
        packed.x = *(uint32_t*)&h0;
        packed.y = *(uint32_t*)&h1;
        *(uint2*)(dst + i) = packed;
    }
}

// ============================================================================
// gemm_p: P[98304, 64] = nx[98304, 128] @ R[64, 128]^T   (one-shot K=128)
// (frozen)
// ============================================================================
#define PP 136
#define P_OFF_B (256 * 272)
#define P_SMEM  (P_OFF_B + 64 * 272)     // 87040

__global__ __launch_bounds__(256, 1)
void gemm_p(const unsigned short* __restrict__ nx, const unsigned short* __restrict__ Rh,
            float* __restrict__ P)
{
    extern __shared__ __align__(128) char smem[];
    const uint32_t sb = smem_u32(smem);
    const int tid = threadIdx.x, wid = tid >> 5, lane = tid & 31;
    const int bm = blockIdx.x * 256;
    const int m0w = (wid & 3) * 64, n0w = (wid >> 2) * 32;

#pragma unroll
    for (int it = 0; it < 20; it++) {
        int cc = it * 256 + tid;
        if (cc < 4096) {
            int row = cc >> 4, ch = cc & 15;
            cp16(sb + row * 272 + ch * 16, nx + (size_t)(bm + row) * 128 + ch * 8);
        } else {
            int idx = cc - 4096, row = idx >> 4, ch = idx & 15;
            cp16(sb + P_OFF_B + row * 272 + ch * 16, Rh + (size_t)row * 128 + ch * 8);
        }
    }
    cp_commit();
    cp_wait0();
    __syncthreads();

    const int rowA = lane & 15, kselA = (lane >> 4) * 8;
    const int grpB = lane >> 3, rowB = lane & 7;
    const int nAdd = rowB + ((grpB & 2) ? 8 : 0);
    const int kAdd = (grpB & 1) * 8;

    float c[4][4][4];
#pragma unroll
    for (int i = 0; i < 4; i++)
#pragma unroll
        for (int j = 0; j < 4; j++)
#pragma unroll
            for (int r = 0; r < 4; r++) c[i][j][r] = 0.f;

#pragma unroll
    for (int ks = 0; ks < 8; ks++) {
        const int kcol = ks * 16;
        uint32_t ah[4][4];
#pragma unroll
        for (int i = 0; i < 4; i++) {
            uint32_t addr = sb + ((m0w + 16 * i + rowA) * PP + kcol + kselA) * 2;
            ldm_x4(ah[i], addr);
        }
        uint32_t bh[2][4];
#pragma unroll
        for (int jj = 0; jj < 2; jj++) {
            uint32_t addr = sb + P_OFF_B + ((n0w + 16 * jj + nAdd) * PP + kcol + kAdd) * 2;
            ldm_x4(bh[jj], addr);
        }
#pragma unroll
        for (int i = 0; i < 4; i++)
#pragma unroll
            for (int j = 0; j < 4; j++)
                mma16816(c[i][j], ah[i], &bh[j >> 1][(j & 1) * 2]);
    }

    const int r0 = lane >> 2, cc2 = (lane & 3) * 2;
#pragma unroll
    for (int i = 0; i < 4; i++) {
#pragma unroll
        for (int j = 0; j < 4; j++) {
            int row = bm + m0w + 16 * i + r0;
            int col = n0w + 8 * j + cc2;
            *(float2*)&P[(size_t)row * 64 + col]       = make_float2(c[i][j][0], c[i][j][1]);
            *(float2*)&P[(size_t)(row + 8) * 64 + col] = make_float2(c[i][j][2], c[i][j][3]);
        }
    }
}

// ============================================================================
// token_post (vectorized, frozen from round 14): feats; scores; out = A @ V.
// ============================================================================
__global__ __launch_bounds__(256)
void token_post(const float* __restrict__ gP, const unsigned short* __restrict__ gqkv,
                unsigned short* __restrict__ gxh)
{
    __shared__ float sQP[16 * 132];
    __shared__ float sKP[8 * 132];
    __shared__ float sV[1024];
    __shared__ float sA[128];

    const int t = threadIdx.x;
    const int token = blockIdx.x, b = token >> 11, s = token & 2047;
    const float INVSF = 0.08838834764831845f;  // 1/sqrt(128)

    const float* P = gP + (size_t)token * 1536;
#pragma unroll
    for (int it = 0; it < 6; it++) {
        int i = it * 256 + t;
        int r = i >> 6, e = i & 63;
        float p = P[i];
        float sp, cp;
        __sincosf(p, &sp, &cp);
        float* dst = (r < 16) ? sQP + r * 132 : sKP + (r - 16) * 132;
        dst[e] = sp * INVSF;
        dst[e + 64] = cp * INVSF;
    }
    {
        const __half* v = (const __half*)(gqkv + (size_t)token * 4096 + 3072);
        uint2 raw = *(const uint2*)(v + t * 4);
        __half2 h0 = *(__half2*)&raw.x;
        __half2 h1 = *(__half2*)&raw.y;
        float2 f0 = __half22float2(h0);
        float2 f1 = __half22float2(h1);
        sV[t * 4 + 0] = f0.x;  sV[t * 4 + 1] = f0.y;
        sV[t * 4 + 2] = f1.x;  sV[t * 4 + 3] = f1.y;
    }
    __syncthreads();

    if (t < 128) {
        int h = t >> 3, i = t & 7;
        const float4* qp = (const float4*)(sQP + h * 132);
        const float4* kp = (const float4*)(sKP + i * 132);
        float acc = 0.f;
#pragma unroll
        for (int f4 = 0; f4 < 32; f4++) {
            float4 a = qp[f4], bb = kp[f4];
            acc += a.x * bb.x;
            acc += a.y * bb.y;
            acc += a.z * bb.z;
            acc += a.w * bb.w;
        }
        sA[t] = 2.0f * acc;
    }
    __syncthreads();

    const size_t obase = ((size_t)b << 22) + (size_t)((s & 15) << 7);
    const int rlo = s >> 4;
#pragma unroll
    for (int it = 0; it < 4; it++) {
        int idx = it * 256 + t;            // 0..1023 (h, d-pair)
        int h = idx >> 6, d = (idx & 63) * 2;
        float ax = 0.f, ay = 0.f;
#pragma unroll
        for (int i = 0; i < 8; i++) {
            float a = sA[h * 8 + i];
            float2 vv = *(const float2*)&sV[i * 128 + d];
            ax += a * vv.x;
            ay += a * vv.y;
        }
        size_t oi = obase + (size_t)(h * 128 + rlo) * 2048 + d;
        *(__half2*)(gxh + oi) = __floats2half2_rn(ax, ay);
    }
}

// ============================================================================
// Launch
// ============================================================================
extern "C" void kernel_launch(void* const* d_in, const int* in_sizes, int n_in,
                              void* d_out, int out_size)
{
    const float* hs = (const float*)d_in[0];
    const float* Wq = (const float*)d_in[1];
    const float* bq = (const float*)d_in[2];
    const float* Wk = (const float*)d_in[3];
    const float* bk = (const float*)d_in[4];
    const float* Wv = (const float*)d_in[5];
    const float* bv = (const float*)d_in[6];
    const float* Wo = (const float*)d_in[7];
    const float* bo = (const float*)d_in[8];
    const float* R  = (const float*)d_in[9];
    float* out = (float*)d_out;
    (void)in_sizes; (void)n_in; (void)out_size;

    unsigned short *qkv, *hsh, *wqkvh, *woh, *rh, *nx, *xh;
    float *gb, *gp;
    cudaGetSymbolAddress((void**)&qkv, g_qkv);
    cudaGetSymbolAddress((void**)&gb, g_bias);
    cudaGetSymbolAddress((void**)&hsh, g_hsh);
    cudaGetSymbolAddress((void**)&wqkvh, g_wqkvh);
    cudaGetSymbolAddress((void**)&woh, g_woh);
    cudaGetSymbolAddress((void**)&rh, g_rh);
    cudaGetSymbolAddress((void**)&nx, g_nx);
    cudaGetSymbolAddress((void**)&gp, g_p);
    cudaGetSymbolAddress((void**)&xh, g_xh);

    cudaFuncSetAttribute(gemm_f16<float>, cudaFuncAttributeMaxDynamicSharedMemorySize, GEMM_SMEM);
    cudaFuncSetAttribute(gemm_f16<__half>, cudaFuncAttributeMaxDynamicSharedMemorySize, GEMM_SMEM);
    cudaFuncSetAttribute(gemm_p, cudaFuncAttributeMaxDynamicSharedMemorySize, P_SMEM);

    // all conversions + bias concat in one launch
    convert_all<<<20492, 256>>>(hs, Wq, Wk, Wv, Wo, R, bq, bk, bv,
                                hsh, wqkvh, woh, rh, gb);

    // fused Q+K+V projection (fp16 out): 128x128 tiles, 2 CTAs/SM
    gemm_f16<__half><<<dim3(32, 32), 256, GEMM_SMEM>>>(
        hsh, wqkvh, gb, (__half*)qkv, 4096, 4096, 2048);

    // performer core: RoPE+norm -> projection GEMM -> feats/scores/out
    token_pre<<<4096, 256>>>(qkv, nx);
    gemm_p<<<384, 256, P_SMEM>>>(nx, rh, gp);
    token_post<<<4096, 256>>>(gp, qkv, xh);

    // output projection (fp32 out)
    gemm_f16<float><<<dim3(16, 32), 256, GEMM_SMEM>>>(
        xh, woh, bo, out, 4096, 2048, 2048);
}

// round 17
// speedup vs baseline: 1.0508x; 1.0112x over previous
#include <cuda_runtime.h>
#include <cuda_fp16.h>
#include <cstdint>
#include <math.h>

// ============================================================================
// Scratch (allocation-free rule: __device__ globals)
// ============================================================================
__device__ unsigned short g_qkv[4096 * 4096];   // fp16: q 0-2047 | k 2048-3071 | v 3072-4095
__device__ float g_bias[4096];                  // bq | bk | bv
__device__ unsigned short g_hsh[8388608];       // hs fp16
__device__ unsigned short g_wqkvh[8388608];     // Wq | Wk | Wv rows x 2048
__device__ unsigned short g_woh[4194304];
__device__ unsigned short g_rh[8192];           // R fp16 [64 x 128]
__device__ unsigned short g_nx[4096 * 24 * 128];// normalized rope'd q/k rows, fp16
__device__ float g_p[4096 * 24 * 64];           // projections, fp32
__device__ unsigned short g_xh[8388608];        // X fp16 (reshape-quirk layout)

// ============================================================================
// Helpers
// ============================================================================
__device__ __forceinline__ uint32_t smem_u32(const void* p) {
    uint32_t a;
    asm("{ .reg .u64 t; cvta.to.shared.u64 t, %1; cvt.u32.u64 %0, t; }" : "=r"(a) : "l"(p));
    return a;
}
__device__ __forceinline__ void cp16(uint32_t soff, const void* g) {
    asm volatile("cp.async.cg.shared.global [%0], [%1], 16;" :: "r"(soff), "l"(g));
}
__device__ __forceinline__ void cp_commit() { asm volatile("cp.async.commit_group;"); }
__device__ __forceinline__ void cp_wait0()  { asm volatile("cp.async.wait_group 0;" ::: "memory"); }
__device__ __forceinline__ void cp_wait1()  { asm volatile("cp.async.wait_group 1;" ::: "memory"); }

__device__ __forceinline__ void ldm_x4(uint32_t* r, uint32_t addr) {
    asm volatile("ldmatrix.sync.aligned.m8n8.x4.shared.b16 {%0,%1,%2,%3}, [%4];"
                 : "=r"(r[0]), "=r"(r[1]), "=r"(r[2]), "=r"(r[3]) : "r"(addr));
}
__device__ __forceinline__ void mma16816(float* c, const uint32_t* a, const uint32_t* b) {
    asm volatile(
        "mma.sync.aligned.m16n8k16.row.col.f32.f16.f16.f32 "
        "{%0,%1,%2,%3}, {%4,%5,%6,%7}, {%8,%9}, {%0,%1,%2,%3};"
        : "+f"(c[0]), "+f"(c[1]), "+f"(c[2]), "+f"(c[3])
        : "r"(a[0]), "r"(a[1]), "r"(a[2]), "r"(a[3]), "r"(b[0]), "r"(b[1]));
}

__device__ __forceinline__ void store_pair(float* C, size_t off, float a, float b) {
    *(float2*)&C[off] = make_float2(a, b);
}
__device__ __forceinline__ void store_pair(__half* C, size_t off, float a, float b) {
    *(__half2*)&C[off] = __floats2half2_rn(a, b);
}

// ============================================================================
// Fused conversion kernel, MLP=4: 4 float4 per thread, loads front-batched
// so each thread keeps 4 independent LDG.128 in flight (hides DRAM latency).
// ============================================================================
#define H0 2097152
#define H1 3145728
#define H2 3670016
#define H3 4194304
#define H4 5242880
#define H5 5244928
#define H6 5245952
#define CVT_BLOCKS 5123                  // 5245952 / 1024 exactly

__global__ __launch_bounds__(256)
void convert_all(const float* __restrict__ hs, const float* __restrict__ Wq,
                 const float* __restrict__ Wk, const float* __restrict__ Wv,
                 const float* __restrict__ Wo, const float* __restrict__ R,
                 const float* __restrict__ bq, const float* __restrict__ bk,
                 const float* __restrict__ bv,
                 unsigned short* __restrict__ hsh, unsigned short* __restrict__ wqkvh,
                 unsigned short* __restrict__ woh, unsigned short* __restrict__ rh,
                 float* __restrict__ gb)
{
    const int base = blockIdx.x * 1024 + threadIdx.x;

    // resolve segment per item
    const float* srcs[4];
    unsigned short* dsts[4];
    int dis[4];
    bool isbias[4];
#pragma unroll
    for (int u = 0; u < 4; u++) {
        int idx = base + u * 256;
        isbias[u] = (idx >= H5);
        if (idx >= H5) {
            int i = idx - H5;
            const float* s;
            int d;
            if (i < 512)      { s = bq; d = i; }
            else if (i < 768) { s = bk; d = i - 512; }
            else              { s = bv; d = i - 768; }
            srcs[u] = s;  dis[u] = d;  dsts[u] = nullptr;
        } else if (idx < H0) { srcs[u] = hs; dis[u] = idx;      dsts[u] = hsh; }
        else if (idx < H1)   { srcs[u] = Wq; dis[u] = idx - H0; dsts[u] = wqkvh; }
        else if (idx < H2)   { srcs[u] = Wk; dis[u] = idx - H1; dsts[u] = wqkvh + 4194304; }
        else if (idx < H3)   { srcs[u] = Wv; dis[u] = idx - H2; dsts[u] = wqkvh + 6291456; }
        else if (idx < H4)   { srcs[u] = Wo; dis[u] = idx - H3; dsts[u] = woh; }
        else                 { srcs[u] = R;  dis[u] = idx - H4; dsts[u] = rh; }
    }

    // front-batched loads: 4 independent LDG.128 in flight
    float4 x[4];
#pragma unroll
    for (int u = 0; u < 4; u++)
        x[u] = ((const float4*)srcs[u])[dis[u]];

    // convert + store
#pragma unroll
    for (int u = 0; u < 4; u++) {
        int idx = base + u * 256;
        if (isbias[u]) {
            ((float4*)gb)[idx - H5] = x[u];
        } else {
            __half2 a = __floats2half2_rn(x[u].x, x[u].y);
            __half2 b = __floats2half2_rn(x[u].z, x[u].w);
            uint2 H;
            H.x = *(uint32_t*)&a;  H.y = *(uint32_t*)&b;
            ((uint2*)dsts[u])[dis[u]] = H;
        }
    }
}

// ============================================================================
// mma.sync fp16 GEMM:  C[M,N] = A[M,K] @ B[N,K]^T + bias[N]
// Block 128x128x64, 256 threads, 8 warps (2m x 4n), warp tile 64x32.
// 3-stage cp.async pipeline, 2 CTAs/SM. FROZEN round-14 body.
// ============================================================================
#define GBK 64
#define APITCH 72
#define ROW_B  144
#define OFF_B  18432                     // A: 128 rows * 144
#define STAGE_B 36864                    // + B: 128 rows * 144
#define NSTAGE 3
#define GEMM_SMEM (NSTAGE * STAGE_B)     // 110592

template <typename OutT>
__global__ __launch_bounds__(256, 2)
void gemm_f16(const unsigned short* __restrict__ Ah, const unsigned short* __restrict__ Bh,
              const float* __restrict__ bias, OutT* __restrict__ C,
              int M, int N, int K)
{
    extern __shared__ __align__(128) char smem[];
    const uint32_t sb = smem_u32(smem);
    const int tid = threadIdx.x, wid = tid >> 5, lane = tid & 31;
    const int bm = blockIdx.y * 128, bn = blockIdx.x * 128;
    const int m0w = (wid & 1) * 64, n0w = (wid >> 1) * 32;

    float c[4][4][4];
#pragma unroll
    for (int i = 0; i < 4; i++)
#pragma unroll
        for (int j = 0; j < 4; j++)
#pragma unroll
            for (int r = 0; r < 4; r++) c[i][j][r] = 0.f;

    const int rowA = lane & 15, kselA = (lane >> 4) * 8;
    const int grpB = lane >> 3, rowB = lane & 7;
    const int nAdd = rowB + ((grpB & 2) ? 8 : 0);
    const int kAdd = (grpB & 1) * 8;

    const int nk = K / GBK;

    auto load_stage = [&](int kt, int buf) {
        const int k0 = kt * GBK;
        const uint32_t stb = sb + buf * STAGE_B;
#pragma unroll
        for (int it = 0; it < 8; it++) {
            int cc = it * 256 + tid;               // 0..2047
            if (cc < 1024) {
                int row = cc >> 3, ch = cc & 7;
                cp16(stb + row * ROW_B + ch * 16,
                     Ah + (size_t)(bm + row) * K + k0 + ch * 8);
            } else {
                int idx = cc - 1024, row = idx >> 3, ch = idx & 7;
                cp16(stb + OFF_B + row * ROW_B + ch * 16,
                     Bh + (size_t)(bn + row) * K + k0 + ch * 8);
            }
        }
    };

    load_stage(0, 0); cp_commit();
    load_stage(1, 1); cp_commit();

    for (int kt = 0; kt < nk; kt++) {
        if (kt + 1 < nk) cp_wait1();
        else             cp_wait0();
        __syncthreads();

        const int buf = kt % 3;
        const uint32_t sA = sb + buf * STAGE_B;
        const uint32_t sB = sA + OFF_B;

#pragma unroll
        for (int kb = 0; kb < 4; kb++) {
            const int kcol = kb * 16;
            uint32_t ah[4][4];
#pragma unroll
            for (int i = 0; i < 4; i++) {
                uint32_t addr = sA + ((m0w + 16 * i + rowA) * APITCH + kcol + kselA) * 2;
                ldm_x4(ah[i], addr);
            }
            uint32_t bh[2][4];
#pragma unroll
            for (int jj = 0; jj < 2; jj++) {
                uint32_t addr = sB + ((n0w + 16 * jj + nAdd) * APITCH + kcol + kAdd) * 2;
                ldm_x4(bh[jj], addr);
            }
#pragma unroll
            for (int i = 0; i < 4; i++)
#pragma unroll
                for (int j = 0; j < 4; j++)
                    mma16816(c[i][j], ah[i], &bh[j >> 1][(j & 1) * 2]);
        }

        if (kt + 2 < nk) { load_stage(kt + 2, (kt + 2) % 3); cp_commit(); }
    }

    const int r0 = lane >> 2, cc2 = (lane & 3) * 2;
#pragma unroll
    for (int i = 0; i < 4; i++) {
#pragma unroll
        for (int j = 0; j < 4; j++) {
            int row = bm + m0w + 16 * i + r0;
            int col = bn + n0w + 8 * j + cc2;
            float b0 = bias[col], b1 = bias[col + 1];
            store_pair(C, (size_t)row * N + col,       c[i][j][0] + b0, c[i][j][1] + b1);
            store_pair(C, (size_t)(row + 8) * N + col, c[i][j][2] + b0, c[i][j][3] + b1);
        }
    }
}

// ============================================================================
// token_pre (vectorized loads, frozen from round 16)
// ============================================================================
__global__ __launch_bounds__(256)
void token_pre(const unsigned short* __restrict__ gqkv, unsigned short* __restrict__ nx)
{
    __shared__ float sX[3072];
    __shared__ float sSin[64], sCos[64];
    __shared__ float sRinv[24];

    const int t = threadIdx.x, w = t >> 5, lane = t & 31;
    const int token = blockIdx.x, s = token & 2047;

    if (t < 64) {
        float iv = (float)exp(-(double)t * 0.14391156831212787);  // ln(1e4)/64
        float ang = (float)s * iv;
        sincosf(ang, &sSin[t], &sCos[t]);
    }
    __syncthreads();

    const size_t base = (size_t)token * 4096;
    const __half* q = (const __half*)(gqkv + base);
#pragma unroll
    for (int it = 0; it < 3; it++) {
        int qd = it * 256 + t;                 // 0..767
        int i = qd * 4;
        int d = i & 127;
        const __half* rowp = q + (i & ~127);
        uint2 vraw = *(const uint2*)(rowp + d);
        int pd = (d < 64) ? d + 64 : d - 64;
        uint2 oraw = *(const uint2*)(rowp + pd);
        const __half* vh = (const __half*)&vraw;
        const __half* oh = (const __half*)&oraw;
#pragma unroll
        for (int e = 0; e < 4; e++) {
            int de = d + e, j = de & 63;
            float val = __half2float(vh[e]);
            float oth = __half2float(oh[e]);
            sX[i + e] = val * sCos[j] + ((de < 64) ? -oth : oth) * sSin[j];
        }
    }
    __syncthreads();

    for (int r = w; r < 24; r += 8) {
        const float* src = sX + r * 128;
        float ss = 0.f;
#pragma unroll
        for (int d = lane; d < 128; d += 32) { float x = src[d]; ss += x * x; }
#pragma unroll
        for (int o = 16; o; o >>= 1) ss += __shfl_xor_sync(0xffffffffu, ss, o);
        if (lane == 0) sRinv[r] = 1.0f / fmaxf(sqrtf(ss), 1e-6f);
    }
    __syncthreads();

    unsigned short* dst = nx + (size_t)token * 3072;
#pragma unroll
    for (int it = 0; it < 3; it++) {
        int qd = it * 256 + t;
        int i = qd * 4;
        int r = i >> 7;
        float rv = sRinv[r];
        __half2 h0 = __floats2half2_rn(sX[i] * rv, sX[i + 1] * rv);
        __half2 h1 = __floats2half2_rn(sX[i + 2] * rv, sX[i + 3] * rv);
        uint2 packed;
        packed.x = *(uint32_t*)&h0;
        packed.y = *(uint32_t*)&h1;
        *(uint2*)(dst + i) = packed;
    }
}

// ============================================================================
// gemm_p: P[98304, 64] = nx[98304, 128] @ R[64, 128]^T  (frozen)
// ============================================================================
#define PP 136
#define P_OFF_B (256 * 272)
#define P_SMEM  (P_OFF_B + 64 * 272)     // 87040

__global__ __launch_bounds__(256, 1)
void gemm_p(const unsigned short* __restrict__ nx, const unsigned short* __restrict__ Rh,
            float* __restrict__ P)
{
    extern __shared__ __align__(128) char smem[];
    const uint32_t sb = smem_u32(smem);
    const int tid = threadIdx.x, wid = tid >> 5, lane = tid & 31;
    const int bm = blockIdx.x * 256;
    const int m0w = (wid & 3) * 64, n0w = (wid >> 2) * 32;

#pragma unroll
    for (int it = 0; it < 20; it++) {
        int cc = it * 256 + tid;
        if (cc < 4096) {
            int row = cc >> 4, ch = cc & 15;
            cp16(sb + row * 272 + ch * 16, nx + (size_t)(bm + row) * 128 + ch * 8);
        } else {
            int idx = cc - 4096, row = idx >> 4, ch = idx & 15;
            cp16(sb + P_OFF_B + row * 272 + ch * 16, Rh + (size_t)row * 128 + ch * 8);
        }
    }
    cp_commit();
    cp_wait0();
    __syncthreads();

    const int rowA = lane & 15, kselA = (lane >> 4) * 8;
    const int grpB = lane >> 3, rowB = lane & 7;
    const int nAdd = rowB + ((grpB & 2) ? 8 : 0);
    const int kAdd = (grpB & 1) * 8;

    float c[4][4][4];
#pragma unroll
    for (int i = 0; i < 4; i++)
#pragma unroll
        for (int j = 0; j < 4; j++)
#pragma unroll
            for (int r = 0; r < 4; r++) c[i][j][r] = 0.f;

#pragma unroll
    for (int ks = 0; ks < 8; ks++) {
        const int kcol = ks * 16;
        uint32_t ah[4][4];
#pragma unroll
        for (int i = 0; i < 4; i++) {
            uint32_t addr = sb + ((m0w + 16 * i + rowA) * PP + kcol + kselA) * 2;
            ldm_x4(ah[i], addr);
        }
        uint32_t bh[2][4];
#pragma unroll
        for (int jj = 0; jj < 2; jj++) {
            uint32_t addr = sb + P_OFF_B + ((n0w + 16 * jj + nAdd) * PP + kcol + kAdd) * 2;
            ldm_x4(bh[jj], addr);
        }
#pragma unroll
        for (int i = 0; i < 4; i++)
#pragma unroll
            for (int j = 0; j < 4; j++)
                mma16816(c[i][j], ah[i], &bh[j >> 1][(j & 1) * 2]);
    }

    const int r0 = lane >> 2, cc2 = (lane & 3) * 2;
#pragma unroll
    for (int i = 0; i < 4; i++) {
#pragma unroll
        for (int j = 0; j < 4; j++) {
            int row = bm + m0w + 16 * i + r0;
            int col = n0w + 8 * j + cc2;
            *(float2*)&P[(size_t)row * 64 + col]       = make_float2(c[i][j][0], c[i][j][1]);
            *(float2*)&P[(size_t)(row + 8) * 64 + col] = make_float2(c[i][j][2], c[i][j][3]);
        }
    }
}

// ============================================================================
// token_post (vectorized, frozen from round 14)
// ============================================================================
__global__ __launch_bounds__(256)
void token_post(const float* __restrict__ gP, const unsigned short* __restrict__ gqkv,
                unsigned short* __restrict__ gxh)
{
    __shared__ float sQP[16 * 132];
    __shared__ float sKP[8 * 132];
    __shared__ float sV[1024];
    __shared__ float sA[128];

    const int t = threadIdx.x;
    const int token = blockIdx.x, b = token >> 11, s = token & 2047;
    const float INVSF = 0.08838834764831845f;  // 1/sqrt(128)

    const float* P = gP + (size_t)token * 1536;
#pragma unroll
    for (int it = 0; it < 6; it++) {
        int i = it * 256 + t;
        int r = i >> 6, e = i & 63;
        float p = P[i];
        float sp, cp;
        __sincosf(p, &sp, &cp);
        float* dst = (r < 16) ? sQP + r * 132 : sKP + (r - 16) * 132;
        dst[e] = sp * INVSF;
        dst[e + 64] = cp * INVSF;
    }
    {
        const __half* v = (const __half*)(gqkv + (size_t)token * 4096 + 3072);
        uint2 raw = *(const uint2*)(v + t * 4);
        __half2 h0 = *(__half2*)&raw.x;
        __half2 h1 = *(__half2*)&raw.y;
        float2 f0 = __half22float2(h0);
        float2 f1 = __half22float2(h1);
        sV[t * 4 + 0] = f0.x;  sV[t * 4 + 1] = f0.y;
        sV[t * 4 + 2] = f1.x;  sV[t * 4 + 3] = f1.y;
    }
    __syncthreads();

    if (t < 128) {
        int h = t >> 3, i = t & 7;
        const float4* qp = (const float4*)(sQP + h * 132);
        const float4* kp = (const float4*)(sKP + i * 132);
        float acc = 0.f;
#pragma unroll
        for (int f4 = 0; f4 < 32; f4++) {
            float4 a = qp[f4], bb = kp[f4];
            acc += a.x * bb.x;
            acc += a.y * bb.y;
            acc += a.z * bb.z;
            acc += a.w * bb.w;
        }
        sA[t] = 2.0f * acc;
    }
    __syncthreads();

    const size_t obase = ((size_t)b << 22) + (size_t)((s & 15) << 7);
    const int rlo = s >> 4;
#pragma unroll
    for (int it = 0; it < 4; it++) {
        int idx = it * 256 + t;            // 0..1023 (h, d-pair)
        int h = idx >> 6, d = (idx & 63) * 2;
        float ax = 0.f, ay = 0.f;
#pragma unroll
        for (int i = 0; i < 8; i++) {
            float a = sA[h * 8 + i];
            float2 vv = *(const float2*)&sV[i * 128 + d];
            ax += a * vv.x;
            ay += a * vv.y;
        }
        size_t oi = obase + (size_t)(h * 128 + rlo) * 2048 + d;
        *(__half2*)(gxh + oi) = __floats2half2_rn(ax, ay);
    }
}

// ============================================================================
// Launch
// ============================================================================
extern "C" void kernel_launch(void* const* d_in, const int* in_sizes, int n_in,
                              void* d_out, int out_size)
{
    const float* hs = (const float*)d_in[0];
    const float* Wq = (const float*)d_in[1];
    const float* bq = (const float*)d_in[2];
    const float* Wk = (const float*)d_in[3];
    const float* bk = (const float*)d_in[4];
    const float* Wv = (const float*)d_in[5];
    const float* bv = (const float*)d_in[6];
    const float* Wo = (const float*)d_in[7];
    const float* bo = (const float*)d_in[8];
    const float* R  = (const float*)d_in[9];
    float* out = (float*)d_out;
    (void)in_sizes; (void)n_in; (void)out_size;

    unsigned short *qkv, *hsh, *wqkvh, *woh, *rh, *nx, *xh;
    float *gb, *gp;
    cudaGetSymbolAddress((void**)&qkv, g_qkv);
    cudaGetSymbolAddress((void**)&gb, g_bias);
    cudaGetSymbolAddress((void**)&hsh, g_hsh);
    cudaGetSymbolAddress((void**)&wqkvh, g_wqkvh);
    cudaGetSymbolAddress((void**)&woh, g_woh);
    cudaGetSymbolAddress((void**)&rh, g_rh);
    cudaGetSymbolAddress((void**)&nx, g_nx);
    cudaGetSymbolAddress((void**)&gp, g_p);
    cudaGetSymbolAddress((void**)&xh, g_xh);

    cudaFuncSetAttribute(gemm_f16<float>, cudaFuncAttributeMaxDynamicSharedMemorySize, GEMM_SMEM);
    cudaFuncSetAttribute(gemm_f16<__half>, cudaFuncAttributeMaxDynamicSharedMemorySize, GEMM_SMEM);
    cudaFuncSetAttribute(gemm_p, cudaFuncAttributeMaxDynamicSharedMemorySize, P_SMEM);

    // all conversions + bias concat in one launch (MLP=4 per thread)
    convert_all<<<CVT_BLOCKS, 256>>>(hs, Wq, Wk, Wv, Wo, R, bq, bk, bv,
                                     hsh, wqkvh, woh, rh, gb);

    // fused Q+K+V projection (fp16 out): 128x128 tiles, 2 CTAs/SM
    gemm_f16<__half><<<dim3(32, 32), 256, GEMM_SMEM>>>(
        hsh, wqkvh, gb, (__half*)qkv, 4096, 4096, 2048);

    // performer core: RoPE+norm -> projection GEMM -> feats/scores/out
    token_pre<<<4096, 256>>>(qkv, nx);
    gemm_p<<<384, 256, P_SMEM>>>(nx, rh, gp);
    token_post<<<4096, 256>>>(gp, qkv, xh);

    // output projection (fp32 out)
    gemm_f16<float><<<dim3(16, 32), 256, GEMM_SMEM>>>(
        xh, woh, bo, out, 4096, 2048, 2048);
}